// round 12
// baseline (speedup 1.0000x reference)
#include <cuda_runtime.h>
#include <cuda_bf16.h>
#include <stdint.h>

#define N_NODES  50000
#define N_EDGES  800000
#define F        128
#define N_GRAPHS 128
#define N_CLASSES 10

// ---------------- scratch (no allocations allowed) ----------------
__device__ __align__(16) float g_HA[N_NODES * F];    // H ping
__device__ __align__(16) float g_HB[N_NODES * F];    // H pong
__device__ float g_dinv[N_NODES];
__device__ int   g_degi[N_NODES];
__device__ int   g_rowbeg[N_NODES];
__device__ int   g_cursor[N_NODES];
__device__ int   g_alloc;
__device__ int   g_csrc[N_EDGES];
__device__ float g_cnorm[N_EDGES];
__device__ __align__(16) float g_gsum[N_GRAPHS * F];
__device__ float g_gcnt[N_GRAPHS];

__device__ __forceinline__ void red_add_v4(float* p, float4 v) {
    asm volatile("red.relaxed.gpu.global.add.v4.f32 [%0], {%1, %2, %3, %4};"
                 :: "l"(p), "f"(v.x), "f"(v.y), "f"(v.z), "f"(v.w)
                 : "memory");
}

// ---------------- packed f32x2 helpers (Blackwell FFMA2) ----------------
__device__ __forceinline__ unsigned long long pack2(float lo, float hi) {
    unsigned long long r;
    asm("mov.b64 %0, {%1, %2};" : "=l"(r) : "f"(lo), "f"(hi));
    return r;
}
__device__ __forceinline__ void fma2(unsigned long long& d,
                                     unsigned long long a, unsigned long long b) {
    asm("fma.rn.f32x2 %0, %1, %2, %0;" : "+l"(d) : "l"(a), "l"(b));
}
__device__ __forceinline__ float2 unpack2(unsigned long long v) {
    float2 r;
    asm("mov.b64 {%0, %1}, %2;" : "=f"(r.x), "=f"(r.y) : "l"(v));
    return r;
}

// ---------------- precompute ----------------
__global__ void k_init(const int* __restrict__ batch) {
    int i = blockIdx.x * blockDim.x + threadIdx.x;
    if (i < N_NODES) {
        g_degi[i] = 0;
        atomicAdd(&g_gcnt[batch[i]], 1.0f);
    }
    if (i < N_GRAPHS * F) g_gsum[i] = 0.0f;
    if (i == 0) g_alloc = 0;
}

__global__ void k_zero_cnt() {
    int i = threadIdx.x;
    if (i < N_GRAPHS) g_gcnt[i] = 0.0f;
}

__global__ void k_deg(const int* __restrict__ ei) {
    int e = blockIdx.x * blockDim.x + threadIdx.x;
    if (e < N_EDGES) atomicAdd(&g_degi[ei[N_EDGES + e]], 1);
}

// warp-aggregated segment allocation: one global atomic per warp
__global__ void k_alloc_seg() {
    int i    = blockIdx.x * blockDim.x + threadIdx.x;
    int lane = threadIdx.x & 31;
    int deg  = (i < N_NODES) ? g_degi[i] : 0;
    int scan = deg;
    #pragma unroll
    for (int o = 1; o < 32; o <<= 1) {
        int t = __shfl_up_sync(0xFFFFFFFFu, scan, o);
        if (lane >= o) scan += t;
    }
    int total = __shfl_sync(0xFFFFFFFFu, scan, 31);
    int base = 0;
    if (lane == 31) base = atomicAdd(&g_alloc, total);
    base = __shfl_sync(0xFFFFFFFFu, base, 31);
    if (i < N_NODES) {
        int pos = base + scan - deg;
        g_rowbeg[i] = pos;
        g_cursor[i] = pos;
        g_dinv[i]   = rsqrtf((float)deg + 1.0f);
    }
}

__global__ void k_fill(const int* __restrict__ ei) {
    int e = blockIdx.x * blockDim.x + threadIdx.x;
    if (e < N_EDGES) {
        int s = ei[e];
        int d = ei[N_EDGES + e];
        int pos = atomicAdd(&g_cursor[d], 1);
        g_csrc[pos]  = s;
        g_cnorm[pos] = g_dinv[s] * g_dinv[d];
    }
}

// ---------------- per-row GCN aggregation (lane-parallel, from src buffer) ---
__device__ __forceinline__ float4 agg_row(const float* __restrict__ Hsrc, int d,
                                          const float* __restrict__ bias,
                                          int lane) {
    const int beg = __ldg(&g_rowbeg[d]);
    const int end = beg + __ldg(&g_degi[d]);
    const float di = __ldg(&g_dinv[d]);

    float4 acc = *(const float4*)&Hsrc[(size_t)d * F + lane * 4];
    float sn = di * di;
    acc.x *= sn; acc.y *= sn; acc.z *= sn; acc.w *= sn;

    int j = beg;
    if (j < end) {
        int   s0 = __ldg(&g_csrc[j]);
        float n0 = __ldg(&g_cnorm[j]);
        float4 v0 = *(const float4*)&Hsrc[(size_t)s0 * F + lane * 4];
        for (j = beg + 1; j < end; j++) {
            int   s1 = __ldg(&g_csrc[j]);
            float n1 = __ldg(&g_cnorm[j]);
            float4 v1 = *(const float4*)&Hsrc[(size_t)s1 * F + lane * 4];
            acc.x += n0 * v0.x; acc.y += n0 * v0.y;
            acc.z += n0 * v0.z; acc.w += n0 * v0.w;
            v0 = v1; n0 = n1;
        }
        acc.x += n0 * v0.x; acc.y += n0 * v0.y;
        acc.z += n0 * v0.z; acc.w += n0 * v0.w;
    }

    float4 bv = *(const float4*)&bias[lane * 4];
    acc.x += bv.x; acc.y += bv.y; acc.z += bv.z; acc.w += bv.w;
    return acc;
}

// ---------------- GEMM core (FFMA2, zipped row-pair X in smem) --------------
__device__ __forceinline__ void gemm_core(const float* sW, const float* sXz,
                                          float* __restrict__ Hout,
                                          int row0, int wp, int cg) {
    unsigned long long acc[4][4];
    #pragma unroll
    for (int i = 0; i < 4; i++)
        #pragma unroll
        for (int j = 0; j < 4; j++) acc[i][j] = 0ull;

    #pragma unroll 4
    for (int k = 0; k < F; k += 2) {
        float4 wa = *(float4*)&sW[k * F + cg * 4];
        float4 wb = *(float4*)&sW[(k + 1) * F + cg * 4];
        unsigned long long wa0 = pack2(wa.x, wa.x), wa1 = pack2(wa.y, wa.y);
        unsigned long long wa2 = pack2(wa.z, wa.z), wa3 = pack2(wa.w, wa.w);
        unsigned long long wb0 = pack2(wb.x, wb.x), wb1 = pack2(wb.y, wb.y);
        unsigned long long wb2 = pack2(wb.z, wb.z), wb3 = pack2(wb.w, wb.w);
        #pragma unroll
        for (int rp = 0; rp < 4; rp++) {
            ulonglong2 xp = *(const ulonglong2*)&sXz[(4 * wp + rp) * 256 + k * 2];
            fma2(acc[rp][0], xp.x, wa0); fma2(acc[rp][1], xp.x, wa1);
            fma2(acc[rp][2], xp.x, wa2); fma2(acc[rp][3], xp.x, wa3);
            fma2(acc[rp][0], xp.y, wb0); fma2(acc[rp][1], xp.y, wb1);
            fma2(acc[rp][2], xp.y, wb2); fma2(acc[rp][3], xp.y, wb3);
        }
    }

    #pragma unroll
    for (int rp = 0; rp < 4; rp++) {
        int r = row0 + 2 * (4 * wp + rp);
        float2 p0 = unpack2(acc[rp][0]);
        float2 p1 = unpack2(acc[rp][1]);
        float2 p2 = unpack2(acc[rp][2]);
        float2 p3 = unpack2(acc[rp][3]);
        if (r < N_NODES)
            *(float4*)&Hout[(size_t)r * F + cg * 4] =
                make_float4(p0.x, p1.x, p2.x, p3.x);
        if (r + 1 < N_NODES)
            *(float4*)&Hout[(size_t)(r + 1) * F + cg * 4] =
                make_float4(p0.y, p1.y, p2.y, p3.y);
    }
}

// ---------------- layer 1 GEMM: HA = X @ W (X from input, no relu) ----------
__global__ void __launch_bounds__(256, 2)
k_gemm0(const float* __restrict__ Xin, const float* __restrict__ W) {
    extern __shared__ float smem[];
    float* sW  = smem;            // 64 KB
    float* sXz = smem + F * F;    // 32 KB

    const int tid  = threadIdx.x;
    const int row0 = blockIdx.x * 64;

    #pragma unroll
    for (int i = 0; i < 16; i++)
        ((float4*)sW)[tid + i * 256] = ((const float4*)W)[tid + i * 256];

    #pragma unroll
    for (int i = 0; i < 4; i++) {
        int idx = tid + i * 256;
        int k4  = idx & 31;
        int rp  = idx >> 5;
        int r0  = row0 + 2 * rp;
        float4 a = make_float4(0.f, 0.f, 0.f, 0.f);
        float4 b = make_float4(0.f, 0.f, 0.f, 0.f);
        if (r0 < N_NODES)     a = ((const float4*)(Xin + (size_t)r0 * F))[k4];
        if (r0 + 1 < N_NODES) b = ((const float4*)(Xin + (size_t)(r0 + 1) * F))[k4];
        float2* dst = (float2*)&sXz[rp * 256 + k4 * 8];
        dst[0] = make_float2(a.x, b.x);
        dst[1] = make_float2(a.y, b.y);
        dst[2] = make_float2(a.z, b.z);
        dst[3] = make_float2(a.w, b.w);
    }
    __syncthreads();

    gemm_core(sW, sXz, g_HA, row0, tid >> 5, tid & 31);
}

// ---------------- fused layer: Hout = relu(agg(Hsrc) + prev_bias) @ W -------
// DIR=0: src=g_HA, dst=g_HB.  DIR=1: src=g_HB, dst=g_HA.
template <int DIR>
__global__ void __launch_bounds__(256, 2)
k_gemm_fused(const float* __restrict__ W, const float* __restrict__ prev_bias) {
    extern __shared__ float smem[];
    float* sW  = smem;            // 64 KB
    float* sXz = smem + F * F;    // 32 KB

    const float* Hsrc = (DIR == 0) ? g_HA : g_HB;
    float*       Hdst = (DIR == 0) ? g_HB : g_HA;

    const int tid  = threadIdx.x;
    const int wp   = tid >> 5;
    const int lane = tid & 31;
    const int row0 = blockIdx.x * 64;

    #pragma unroll
    for (int i = 0; i < 16; i++)
        ((float4*)sW)[tid + i * 256] = ((const float4*)W)[tid + i * 256];

    // each warp aggregates its 8 rows (row pairs 4wp..4wp+3), zip-writes pairs
    float4 held = make_float4(0.f, 0.f, 0.f, 0.f);
    #pragma unroll
    for (int i = 0; i < 8; i++) {
        int d = row0 + wp * 8 + i;
        float4 a = make_float4(0.f, 0.f, 0.f, 0.f);
        if (d < N_NODES) {
            a = agg_row(Hsrc, d, prev_bias, lane);
            a.x = fmaxf(a.x, 0.f); a.y = fmaxf(a.y, 0.f);
            a.z = fmaxf(a.z, 0.f); a.w = fmaxf(a.w, 0.f);
        }
        if ((i & 1) == 0) {
            held = a;
        } else {
            int rp = 4 * wp + (i >> 1);
            float2* dst = (float2*)&sXz[rp * 256 + lane * 8];
            dst[0] = make_float2(held.x, a.x);
            dst[1] = make_float2(held.y, a.y);
            dst[2] = make_float2(held.z, a.z);
            dst[3] = make_float2(held.w, a.w);
        }
    }
    __syncthreads();

    gemm_core(sW, sXz, Hdst, row0, wp, lane);
}

// ---------------- final aggregate + mean-pool accumulation ------------------
__global__ void __launch_bounds__(256)
k_agg_pool(const float* __restrict__ bias, const int* __restrict__ batch) {
    const int warp = (blockIdx.x * blockDim.x + threadIdx.x) >> 5;
    const int lane = threadIdx.x & 31;
    if (warp >= N_NODES) return;
    float4 acc = agg_row(g_HA, warp, bias, lane);
    int g = __ldg(&batch[warp]);
    red_add_v4(&g_gsum[g * F + lane * 4], acc);
}

// ---------------- head ----------------
__global__ void k_final(const float* __restrict__ lin_w,
                        const float* __restrict__ lin_b,
                        float* __restrict__ out) {
    int g = blockIdx.x;
    int c = threadIdx.x;
    if (c >= N_CLASSES) return;
    float cnt = fmaxf(g_gcnt[g], 1.0f);
    float acc = 0.f;
    #pragma unroll 8
    for (int f = 0; f < F; f++)
        acc += g_gsum[g * F + f] * __ldg(&lin_w[f * N_CLASSES + c]);
    out[g * N_CLASSES + c] = acc / cnt + lin_b[c];
}

// ---------------- host ----------------
extern "C" void kernel_launch(void* const* d_in, const int* in_sizes, int n_in,
                              void* d_out, int out_size) {
    const float* x     = (const float*)d_in[0];
    const int*   ei    = (const int*)d_in[1];
    const int*   batch = (const int*)d_in[2];
    const float* w1 = (const float*)d_in[3];
    const float* b1 = (const float*)d_in[4];
    const float* w2 = (const float*)d_in[5];
    const float* b2 = (const float*)d_in[6];
    const float* w3 = (const float*)d_in[7];
    const float* b3 = (const float*)d_in[8];
    const float* lw = (const float*)d_in[9];
    const float* lb = (const float*)d_in[10];
    float* out = (float*)d_out;

    const int SMEM = (F * F + 64 * F) * (int)sizeof(float);   // 96 KB
    cudaFuncSetAttribute(k_gemm0, cudaFuncAttributeMaxDynamicSharedMemorySize, SMEM);
    cudaFuncSetAttribute(k_gemm_fused<0>, cudaFuncAttributeMaxDynamicSharedMemorySize, SMEM);
    cudaFuncSetAttribute(k_gemm_fused<1>, cudaFuncAttributeMaxDynamicSharedMemorySize, SMEM);

    const int GB = (N_NODES + 63) / 64;
    const int AB = (N_NODES + 7) / 8;

    k_zero_cnt<<<1, N_GRAPHS>>>();
    k_init<<<(N_NODES + 255) / 256, 256>>>(batch);
    k_deg<<<(N_EDGES + 255) / 256, 256>>>(ei);
    k_alloc_seg<<<(N_NODES + 255) / 256, 256>>>();
    k_fill<<<(N_EDGES + 255) / 256, 256>>>(ei);

    k_gemm0<<<GB, 256, SMEM>>>(x, w1);               // layer 1 GEMM      -> HA
    k_gemm_fused<0><<<GB, 256, SMEM>>>(w2, b1);      // agg(HA) + GEMM    -> HB
    k_gemm_fused<1><<<GB, 256, SMEM>>>(w3, b2);      // agg(HB) + GEMM    -> HA
    k_agg_pool<<<AB, 256>>>(b3, batch);              // agg(HA) + mean-pool
    k_final<<<N_GRAPHS, 32>>>(lw, lb, out);
}

// round 13
// speedup vs baseline: 1.0788x; 1.0788x over previous
#include <cuda_runtime.h>
#include <cuda_bf16.h>
#include <stdint.h>

#define N_NODES  50000
#define N_EDGES  800000
#define F        128
#define N_GRAPHS 128
#define N_CLASSES 10

// ---------------- scratch (no allocations allowed) ----------------
__device__ __align__(16) float g_H[N_NODES * F];     // GEMM output
__device__ __align__(16) float g_ACC[N_NODES * F];   // aggregated layer output
__device__ float g_dinv[N_NODES];
__device__ int   g_degi[N_NODES];
__device__ int   g_rowbeg[N_NODES];
__device__ int   g_cursor[N_NODES];
__device__ int   g_alloc;
__device__ int   g_csrc[N_EDGES];
__device__ float g_cnorm[N_EDGES];
__device__ __align__(16) float g_gsum[N_GRAPHS * F];
__device__ float g_gcnt[N_GRAPHS];

__device__ __forceinline__ void red_add_v4(float* p, float4 v) {
    asm volatile("red.relaxed.gpu.global.add.v4.f32 [%0], {%1, %2, %3, %4};"
                 :: "l"(p), "f"(v.x), "f"(v.y), "f"(v.z), "f"(v.w)
                 : "memory");
}

// ---------------- packed f32x2 helpers (Blackwell FFMA2) ----------------
__device__ __forceinline__ unsigned long long pack2(float lo, float hi) {
    unsigned long long r;
    asm("mov.b64 %0, {%1, %2};" : "=l"(r) : "f"(lo), "f"(hi));
    return r;
}
__device__ __forceinline__ void fma2(unsigned long long& d,
                                     unsigned long long a, unsigned long long b) {
    asm("fma.rn.f32x2 %0, %1, %2, %0;" : "+l"(d) : "l"(a), "l"(b));
}
__device__ __forceinline__ float2 unpack2(unsigned long long v) {
    float2 r;
    asm("mov.b64 {%0, %1}, %2;" : "=f"(r.x), "=f"(r.y) : "l"(v));
    return r;
}

// ---------------- precompute ----------------
__global__ void k_init(const int* __restrict__ batch) {
    int i = blockIdx.x * blockDim.x + threadIdx.x;
    if (i < N_NODES) {
        g_degi[i] = 0;
        atomicAdd(&g_gcnt[batch[i]], 1.0f);
    }
    if (i < N_GRAPHS * F) g_gsum[i] = 0.0f;
    if (i == 0) g_alloc = 0;
}

__global__ void k_zero_cnt() {
    int i = threadIdx.x;
    if (i < N_GRAPHS) g_gcnt[i] = 0.0f;
}

__global__ void k_deg(const int* __restrict__ ei) {
    int e = blockIdx.x * blockDim.x + threadIdx.x;
    if (e < N_EDGES) atomicAdd(&g_degi[ei[N_EDGES + e]], 1);
}

// warp-aggregated segment allocation: one global atomic per warp
__global__ void k_alloc_seg() {
    int i    = blockIdx.x * blockDim.x + threadIdx.x;
    int lane = threadIdx.x & 31;
    int deg  = (i < N_NODES) ? g_degi[i] : 0;
    int scan = deg;
    #pragma unroll
    for (int o = 1; o < 32; o <<= 1) {
        int t = __shfl_up_sync(0xFFFFFFFFu, scan, o);
        if (lane >= o) scan += t;
    }
    int total = __shfl_sync(0xFFFFFFFFu, scan, 31);
    int base = 0;
    if (lane == 31) base = atomicAdd(&g_alloc, total);
    base = __shfl_sync(0xFFFFFFFFu, base, 31);
    if (i < N_NODES) {
        int pos = base + scan - deg;
        g_rowbeg[i] = pos;
        g_cursor[i] = pos;
        g_dinv[i]   = rsqrtf((float)deg + 1.0f);
    }
}

__global__ void k_fill(const int* __restrict__ ei) {
    int e = blockIdx.x * blockDim.x + threadIdx.x;
    if (e < N_EDGES) {
        int s = ei[e];
        int d = ei[N_EDGES + e];
        int pos = atomicAdd(&g_cursor[d], 1);
        g_csrc[pos]  = s;
        g_cnorm[pos] = g_dinv[s] * g_dinv[d];
    }
}

// ---------------- GEMM: H = act(X) @ W  (FFMA2, 8 row-pairs x 2 cols/warp) --
// MODE 0: read Xin (no relu). MODE 1: read relu(g_ACC).
// Block: 64 rows x 128 cols, 256 threads, full K=128 in smem (96 KB, 2 CTA/SM).
// X zipped by row pairs (sXz[rp][k][2]); warp = (row-group 0..3) x (col-half
// 0..1); each lane owns 2 cols and 8 row-pairs: per 2k only 4 W dup-packs
// serve 32 FFMA2 (payload fraction ~70% vs 53% in the 4x4 layout).
template <int MODE>
__global__ void __launch_bounds__(256, 2)
k_gemm(const float* __restrict__ Xin, const float* __restrict__ W) {
    extern __shared__ float smem[];
    float* sW  = smem;            // [128 k][128 n] = 64 KB
    float* sXz = smem + F * F;    // [32 rp][128 k][2] = 32 KB

    const int tid  = threadIdx.x;
    const int row0 = blockIdx.x * 64;

    #pragma unroll
    for (int i = 0; i < 16; i++)
        ((float4*)sW)[tid + i * 256] = ((const float4*)W)[tid + i * 256];

    const float* src = (MODE == 0) ? Xin : g_ACC;
    #pragma unroll
    for (int i = 0; i < 4; i++) {
        int idx = tid + i * 256;          // over 32 k4-groups x 32 row-pairs
        int k4  = idx & 31;
        int rp  = idx >> 5;
        int r0  = row0 + 2 * rp;
        float4 a = make_float4(0.f, 0.f, 0.f, 0.f);
        float4 b = make_float4(0.f, 0.f, 0.f, 0.f);
        if (r0 < N_NODES)     a = ((const float4*)(src + (size_t)r0 * F))[k4];
        if (r0 + 1 < N_NODES) b = ((const float4*)(src + (size_t)(r0 + 1) * F))[k4];
        if (MODE == 1) {
            a.x = fmaxf(a.x, 0.f); a.y = fmaxf(a.y, 0.f);
            a.z = fmaxf(a.z, 0.f); a.w = fmaxf(a.w, 0.f);
            b.x = fmaxf(b.x, 0.f); b.y = fmaxf(b.y, 0.f);
            b.z = fmaxf(b.z, 0.f); b.w = fmaxf(b.w, 0.f);
        }
        float2* dst = (float2*)&sXz[rp * 256 + k4 * 8];
        dst[0] = make_float2(a.x, b.x);
        dst[1] = make_float2(a.y, b.y);
        dst[2] = make_float2(a.z, b.z);
        dst[3] = make_float2(a.w, b.w);
    }
    __syncthreads();

    const int wp   = tid >> 5;
    const int lane = tid & 31;
    const int rg   = wp & 3;          // row group: row-pairs 8rg..8rg+7
    const int c0   = (wp >> 2) * 64 + lane * 2;   // 2 cols per lane

    unsigned long long acc[8][2];     // [row-pair][col], pair packed over rows
    #pragma unroll
    for (int i = 0; i < 8; i++) { acc[i][0] = 0ull; acc[i][1] = 0ull; }

    #pragma unroll 4
    for (int k = 0; k < F; k += 2) {
        float2 wa = *(float2*)&sW[k * F + c0];
        float2 wb = *(float2*)&sW[(k + 1) * F + c0];
        unsigned long long w00 = pack2(wa.x, wa.x);   // k,   col c0
        unsigned long long w01 = pack2(wa.y, wa.y);   // k,   col c0+1
        unsigned long long w10 = pack2(wb.x, wb.x);   // k+1, col c0
        unsigned long long w11 = pack2(wb.y, wb.y);   // k+1, col c0+1
        #pragma unroll
        for (int rp = 0; rp < 8; rp++) {
            ulonglong2 xp = *(const ulonglong2*)&sXz[(8 * rg + rp) * 256 + k * 2];
            fma2(acc[rp][0], xp.x, w00); fma2(acc[rp][1], xp.x, w01);
            fma2(acc[rp][0], xp.y, w10); fma2(acc[rp][1], xp.y, w11);
        }
    }

    #pragma unroll
    for (int rp = 0; rp < 8; rp++) {
        int r = row0 + 16 * rg + 2 * rp;
        float2 pa = unpack2(acc[rp][0]);   // (row r, row r+1) @ col c0
        float2 pb = unpack2(acc[rp][1]);   // (row r, row r+1) @ col c0+1
        if (r < N_NODES)
            *(float2*)&g_H[(size_t)r * F + c0] = make_float2(pa.x, pb.x);
        if (r + 1 < N_NODES)
            *(float2*)&g_H[(size_t)(r + 1) * F + c0] = make_float2(pa.y, pb.y);
    }
}

// ---------------- aggregate: ACC[d] = sum_in norm*H[s] + dinv[d]^2*H[d] + b ----
// POOL=1: RED the result into g_gsum[batch[d]] instead of storing ACC.
template <int POOL>
__global__ void __launch_bounds__(256)
k_aggregate(const float* __restrict__ bias, const int* __restrict__ batch) {
    const int warp = (blockIdx.x * blockDim.x + threadIdx.x) >> 5;
    const int lane = threadIdx.x & 31;
    if (warp >= N_NODES) return;
    const int d = warp;

    const int beg = __ldg(&g_rowbeg[d]);
    const int end = beg + __ldg(&g_degi[d]);
    const float di = __ldg(&g_dinv[d]);

    float4 acc = *(const float4*)&g_H[(size_t)d * F + lane * 4];
    float sn = di * di;
    acc.x *= sn; acc.y *= sn; acc.z *= sn; acc.w *= sn;

    int j = beg;
    if (j < end) {
        int   s0 = __ldg(&g_csrc[j]);
        float n0 = __ldg(&g_cnorm[j]);
        float4 v0 = *(const float4*)&g_H[(size_t)s0 * F + lane * 4];
        for (j = beg + 1; j < end; j++) {
            int   s1 = __ldg(&g_csrc[j]);
            float n1 = __ldg(&g_cnorm[j]);
            float4 v1 = *(const float4*)&g_H[(size_t)s1 * F + lane * 4];
            acc.x += n0 * v0.x; acc.y += n0 * v0.y;
            acc.z += n0 * v0.z; acc.w += n0 * v0.w;
            v0 = v1; n0 = n1;
        }
        acc.x += n0 * v0.x; acc.y += n0 * v0.y;
        acc.z += n0 * v0.z; acc.w += n0 * v0.w;
    }

    float4 bv = *(const float4*)&bias[lane * 4];
    acc.x += bv.x; acc.y += bv.y; acc.z += bv.z; acc.w += bv.w;

    if (POOL) {
        int g = __ldg(&batch[d]);
        red_add_v4(&g_gsum[g * F + lane * 4], acc);
    } else {
        *(float4*)&g_ACC[(size_t)d * F + lane * 4] = acc;
    }
}

// ---------------- head ----------------
__global__ void k_final(const float* __restrict__ lin_w,
                        const float* __restrict__ lin_b,
                        float* __restrict__ out) {
    int g = blockIdx.x;
    int c = threadIdx.x;
    if (c >= N_CLASSES) return;
    float cnt = fmaxf(g_gcnt[g], 1.0f);
    float acc = 0.f;
    #pragma unroll 8
    for (int f = 0; f < F; f++)
        acc += g_gsum[g * F + f] * __ldg(&lin_w[f * N_CLASSES + c]);
    out[g * N_CLASSES + c] = acc / cnt + lin_b[c];
}

// ---------------- host ----------------
extern "C" void kernel_launch(void* const* d_in, const int* in_sizes, int n_in,
                              void* d_out, int out_size) {
    const float* x     = (const float*)d_in[0];
    const int*   ei    = (const int*)d_in[1];
    const int*   batch = (const int*)d_in[2];
    const float* w1 = (const float*)d_in[3];
    const float* b1 = (const float*)d_in[4];
    const float* w2 = (const float*)d_in[5];
    const float* b2 = (const float*)d_in[6];
    const float* w3 = (const float*)d_in[7];
    const float* b3 = (const float*)d_in[8];
    const float* lw = (const float*)d_in[9];
    const float* lb = (const float*)d_in[10];
    float* out = (float*)d_out;

    const int SMEM = (F * F + 64 * F) * (int)sizeof(float);   // 96 KB
    cudaFuncSetAttribute(k_gemm<0>, cudaFuncAttributeMaxDynamicSharedMemorySize, SMEM);
    cudaFuncSetAttribute(k_gemm<1>, cudaFuncAttributeMaxDynamicSharedMemorySize, SMEM);

    const int GB = (N_NODES + 63) / 64;
    const int AB = (N_NODES + 7) / 8;

    k_zero_cnt<<<1, N_GRAPHS>>>();
    k_init<<<(N_NODES + 255) / 256, 256>>>(batch);
    k_deg<<<(N_EDGES + 255) / 256, 256>>>(ei);
    k_alloc_seg<<<(N_NODES + 255) / 256, 256>>>();
    k_fill<<<(N_EDGES + 255) / 256, 256>>>(ei);

    k_gemm<0><<<GB, 256, SMEM>>>(x, w1);
    k_aggregate<0><<<AB, 256>>>(b1, batch);
    k_gemm<1><<<GB, 256, SMEM>>>(x, w2);
    k_aggregate<0><<<AB, 256>>>(b2, batch);
    k_gemm<1><<<GB, 256, SMEM>>>(x, w3);
    k_aggregate<1><<<AB, 256>>>(b3, batch);

    k_final<<<N_GRAPHS, 32>>>(lw, lb, out);
}